// round 2
// baseline (speedup 1.0000x reference)
#include <cuda_runtime.h>
#include <cuda_bf16.h>
#include <math.h>

// ---------------- geometry ----------------
#define NB     2
#define NC     8
#define NV     360
#define ND     512
#define RR     11           // taps
#define HID    176          // hidden channels
#define OC     88           // conv2 out channels = RR*NC
#define NP     (NV*ND)      // 184320 sample columns
#define LL     (NP*RR)      // 2027520
#define NIDX   (128*128*360)// 5898240 indices
#define DT     256          // d-tile per block
#define HCP    88           // hidden channels per phase
#define HP     264          // smem pitch (floats) for x_s / h_s
#define YP     261          // y staging pitch (conflict-free: 261 mod 32 = 5)

// scratch (no cudaMalloc allowed)
__device__ float g_A[2u * (unsigned)LL * 8u];        // [b][p][r][c]  ~130MB
// duplicated/packed fc2 weights: [c(8)][rh(2)][hc(176)][18 pairs][2]
__device__ float g_w2d[8 * 2 * 176 * 18 * 2];

// ---------------- f32x2 helpers ----------------
__device__ __forceinline__ void ffma2(unsigned long long& c,
                                      unsigned long long a,
                                      unsigned long long b) {
    asm("fma.rn.f32x2 %0, %1, %2, %0;" : "+l"(c) : "l"(a), "l"(b));
}
__device__ __forceinline__ unsigned long long pack2(float lo, float hi) {
    unsigned long long r;
    asm("mov.b64 %0, {%1, %2};" : "=l"(r) : "f"(lo), "f"(hi));
    return r;
}
__device__ __forceinline__ float2 unpack2(unsigned long long v) {
    float2 f;
    asm("mov.b64 {%0, %1}, %2;" : "=f"(f.x), "=f"(f.y) : "l"(v));
    return f;
}

// ---- repack fc2_w [88][176][3] -> g_w2d[c][rh][hc][k2=rl*3+t] dup pairs ----
__global__ void repack_w2(const float* __restrict__ w2) {
    int idx = blockIdx.x * 256 + threadIdx.x;           // over 8*2*176*18
    if (idx >= 8 * 2 * 176 * 18) return;
    int k2 = idx % 18;
    int t  = k2 % 3;
    int rl = k2 / 3;
    int hc = (idx / 18) % 176;
    int rh = (idx / (18 * 176)) % 2;
    int c  = idx / (18 * 176 * 2);
    int r  = rh * 6 + rl;                               // r in [0,12), r==11 padded
    float v = 0.f;
    if (r < RR) v = w2[(((c * RR + r) * HID) + hc) * 3 + t];
    g_w2d[idx * 2 + 0] = v;
    g_w2d[idx * 2 + 1] = v;
}

// ---------------- fused conv1+gelu+conv2, writes A[b][p][r][c] ----------------
__global__ __launch_bounds__(512, 1)
void conv_fused(const float* __restrict__ input,
                const float* __restrict__ w1,
                const float* __restrict__ b1,
                const float* __restrict__ b2) {
    extern __shared__ float smem[];
    float* x_s = smem;                 // [8][264]   (260 used)
    float* h_s = smem + 8 * HP;        // [88][264]  (258 used)

    const int tid  = threadIdx.x;
    const int blk  = blockIdx.x;
    const int bv   = blk >> 1;
    const int tile = blk & 1;
    const int d0   = tile * DT;
    const int b    = bv / NV;
    const int v    = bv - b * NV;

    // ---- load x halo: x_s[ci][j] = input[b,ci,v, d0-2+j], j in [0,260) ----
    for (int i = tid; i < 8 * HP; i += 512) {
        int ci = i / HP, j = i - ci * HP;
        int dG = d0 - 2 + j;
        float val = 0.f;
        if (j < 260 && (unsigned)dG < (unsigned)ND)
            val = input[(((size_t)(b * NC + ci) * NV + v) * ND) + dG];
        x_s[i] = val;
    }

    const int wid   = tid >> 5;
    const int lane  = tid & 31;
    const int c     = wid & 7;       // output channel
    const int rh    = wid >> 3;      // r-half: 0 -> r 0..5, 1 -> r 6..11(pad)
    const int dbase = lane * 8;      // 8 d positions per lane

    // ---- acc init with bias ----
    unsigned long long acc[6][4];
#pragma unroll
    for (int r = 0; r < 6; ++r) {
        int rg = rh * 6 + r;
        float bb = (rg < RR) ? b2[c * RR + rg] : 0.f;
#pragma unroll
        for (int i = 0; i < 4; ++i) acc[r][i] = pack2(bb, bb);
    }

    __syncthreads();

    for (int ph = 0; ph < 2; ++ph) {
        // ---- conv1 + exact gelu -> h_s[hcl][dd], dd in [0,258) ----
        for (int idx = tid; idx < HCP * 258; idx += 512) {
            int hcl = idx / 258;
            int dd  = idx - hcl * 258;
            int hc  = ph * HCP + hcl;
            int dG  = d0 - 1 + dd;
            float s = 0.f;
            if ((unsigned)dG < (unsigned)ND) {
                s = b1[hc];
                const float* wr = w1 + hc * 24;
#pragma unroll
                for (int ci = 0; ci < 8; ++ci) {
                    const float* xr = x_s + ci * HP + dd;  // x[dG-1..dG+1]
                    s = fmaf(xr[0], wr[ci * 3 + 0], s);
                    s = fmaf(xr[1], wr[ci * 3 + 1], s);
                    s = fmaf(xr[2], wr[ci * 3 + 2], s);
                }
                s = 0.5f * s * (1.0f + erff(s * 0.70710678118654752f));
            }
            h_s[hcl * HP + dd] = s;
        }
        __syncthreads();

        // ---- conv2 accumulate over this phase's 88 hidden channels ----
        const ulonglong2* wp = ((const ulonglong2*)g_w2d) +
                               ((size_t)(c * 2 + rh) * HID + (size_t)ph * HCP) * 9;
        for (int hcl = 0; hcl < HCP; ++hcl, wp += 9) {
            const float* hr = h_s + hcl * HP + dbase;
            float4 ha = *(const float4*)hr;          // h[j0..j3]
            float4 hb = *(const float4*)(hr + 4);    // h[j4..j7]
            float2 he = *(const float2*)(hr + 8);    // h[j8..j9]

            // d-pair operands for the 3 taps (taps 0 and 2 naturally aligned)
            unsigned long long pk0[4] = {pack2(ha.x, ha.y), pack2(ha.z, ha.w),
                                         pack2(hb.x, hb.y), pack2(hb.z, hb.w)};
            unsigned long long pk1[4] = {pack2(ha.y, ha.z), pack2(ha.w, hb.x),
                                         pack2(hb.y, hb.z), pack2(hb.w, he.x)};
            unsigned long long pk2[4] = {pack2(ha.z, ha.w), pack2(hb.x, hb.y),
                                         pack2(hb.z, hb.w), pack2(he.x, he.y)};

            // weights: 18 dup-pairs = 9x16B; split load to limit liveness
            ulonglong2 wa0 = wp[0], wa1 = wp[1], wa2 = wp[2], wa3 = wp[3], wa4 = wp[4];
            {   // r = 0..2  (pair indices 0..8)
                unsigned long long w00 = wa0.x, w01 = wa0.y, w02 = wa1.x;
                unsigned long long w10 = wa1.y, w11 = wa2.x, w12 = wa2.y;
                unsigned long long w20 = wa3.x, w21 = wa3.y, w22 = wa4.x;
#pragma unroll
                for (int i = 0; i < 4; ++i) {
                    ffma2(acc[0][i], pk0[i], w00);
                    ffma2(acc[0][i], pk1[i], w01);
                    ffma2(acc[0][i], pk2[i], w02);
                    ffma2(acc[1][i], pk0[i], w10);
                    ffma2(acc[1][i], pk1[i], w11);
                    ffma2(acc[1][i], pk2[i], w12);
                    ffma2(acc[2][i], pk0[i], w20);
                    ffma2(acc[2][i], pk1[i], w21);
                    ffma2(acc[2][i], pk2[i], w22);
                }
            }
            ulonglong2 wb0 = wp[5], wb1 = wp[6], wb2 = wp[7], wb3 = wp[8];
            {   // r = 3..5  (pair indices 9..17)
                unsigned long long w30 = wa4.y, w31 = wb0.x, w32 = wb0.y;
                unsigned long long w40 = wb1.x, w41 = wb1.y, w42 = wb2.x;
                unsigned long long w50 = wb2.y, w51 = wb3.x, w52 = wb3.y;
#pragma unroll
                for (int i = 0; i < 4; ++i) {
                    ffma2(acc[3][i], pk0[i], w30);
                    ffma2(acc[3][i], pk1[i], w31);
                    ffma2(acc[3][i], pk2[i], w32);
                    ffma2(acc[4][i], pk0[i], w40);
                    ffma2(acc[4][i], pk1[i], w41);
                    ffma2(acc[4][i], pk2[i], w42);
                    ffma2(acc[5][i], pk0[i], w50);
                    ffma2(acc[5][i], pk1[i], w51);
                    ffma2(acc[5][i], pk2[i], w52);
                }
            }
        }
        __syncthreads();   // h_s consumed; next phase may overwrite
    }

    // ---- epilogue: transpose-stage y into smem (reuse whole smem) ----
    float* y_s = smem;     // [88][YP=261], 88*261 = 22968 <= 25344 floats avail
#pragma unroll
    for (int r = 0; r < 6; ++r) {
        int rg = rh * 6 + r;
        if (rg < RR) {
            int col = rg * 8 + c;
            float* yr = y_s + (size_t)col * YP + dbase;
#pragma unroll
            for (int i = 0; i < 4; ++i) {
                float2 f = unpack2(acc[r][i]);
                yr[2 * i + 0] = f.x;
                yr[2 * i + 1] = f.y;
            }
        }
    }
    __syncthreads();

    // coalesced global write: A[b][p0..p0+255][r][c]
    size_t gbase = ((size_t)b * NP + (size_t)v * ND + d0) * OC;
    for (int i = tid; i < DT * OC; i += 512) {
        int od  = i / OC;
        int col = i - od * OC;
        g_A[gbase + i] = y_s[(size_t)col * YP + od];
    }
}

// ---------------- gather / interpolation ----------------
__global__ __launch_bounds__(256)
void gather_kernel(const float* __restrict__ idxs, float* __restrict__ out) {
    int j = blockIdx.x * 256 + threadIdx.x;
    if (j >= NIDX) return;

    float t  = idxs[j];
    float il = floorf(t);
    float w  = t - il;
    float w5 = w * 5.0f;
    float fw = floorf(w5);
    float lw = w5 - fw;

    int li = (int)(il * 11.0f + 5.0f + fw);
    int hi = li + 6;
    if (hi >= LL - 1) hi = LL - 2;

    float omlw = 1.0f - lw;
    float omw  = 1.0f - w;

#pragma unroll
    for (int b = 0; b < 2; ++b) {
        const float* Ab = g_A + (size_t)b * (size_t)LL * 8u;
        const float4* plo = (const float4*)(Ab + (size_t)li * 8u);
        const float4* phi = (const float4*)(Ab + (size_t)hi * 8u);
        float4 v0 = __ldg(plo + 0);   // A[li][0..3]
        float4 v1 = __ldg(plo + 1);   // A[li][4..7]
        float4 v2 = __ldg(plo + 2);   // A[li+1][0..3]
        float4 v3 = __ldg(plo + 3);   // A[li+1][4..7]
        float4 u0 = __ldg(phi + 0);
        float4 u1 = __ldg(phi + 1);
        float4 u2 = __ldg(phi + 2);
        float4 u3 = __ldg(phi + 3);

        float a0[8]  = {v0.x, v0.y, v0.z, v0.w, v1.x, v1.y, v1.z, v1.w};
        float a1[8]  = {v2.x, v2.y, v2.z, v2.w, v3.x, v3.y, v3.z, v3.w};
        float b0[8]  = {u0.x, u0.y, u0.z, u0.w, u1.x, u1.y, u1.z, u1.w};
        float b1v[8] = {u2.x, u2.y, u2.z, u2.w, u3.x, u3.y, u3.z, u3.w};

        size_t obase = (size_t)b * 8u * (size_t)NIDX + (size_t)j;
#pragma unroll
        for (int cc = 0; cc < 8; ++cc) {
            float low  = a0[cc] * omlw + a1[cc]  * lw;
            float high = b0[cc] * omlw + b1v[cc] * lw;
            out[obase + (size_t)cc * (size_t)NIDX] = low * omw + high * w;
        }
    }
}

// ---------------- launch ----------------
extern "C" void kernel_launch(void* const* d_in, const int* in_sizes, int n_in,
                              void* d_out, int out_size) {
    const float* input = (const float*)d_in[0];   // [2,8,360,512]
    const float* idxs  = (const float*)d_in[1];   // [5898240]
    const float* fc1w  = (const float*)d_in[2];   // [176,8,3]
    const float* fc1b  = (const float*)d_in[3];   // [176]
    const float* fc2w  = (const float*)d_in[4];   // [88,176,3]
    const float* fc2b  = (const float*)d_in[5];   // [88]
    float* out = (float*)d_out;

    static const int smem_bytes = (8 * HP + HCP * HP) * sizeof(float); // 101376
    cudaFuncSetAttribute(conv_fused, cudaFuncAttributeMaxDynamicSharedMemorySize,
                         smem_bytes);

    repack_w2<<<(8 * 2 * 176 * 18 + 255) / 256, 256>>>(fc2w);
    conv_fused<<<NB * NV * (ND / DT), 512, smem_bytes>>>(input, fc1w, fc1b, fc2b);
    gather_kernel<<<NIDX / 256, 256>>>(idxs, out);
}